// round 1
// baseline (speedup 1.0000x reference)
#include <cuda_runtime.h>
#include <cstdint>

// Elman RNN: h_{t+1} = tanh(x_t @ W_ih^T + b_ih + h_t @ W_hh^T + b_hh)
// out = sigmoid(h_T @ fc_w^T + fc_b)
// N=2048, T=512, I=32, H=64, O=1. One block per sample, 64 threads (lane j = hidden unit j).
// Weights held per-lane in registers as packed f32x2 pairs; h||x_t in double-buffered smem.

#define T_STEPS 512
#define I_DIM   32
#define H_DIM   64
#define K_TOT   96   // H + I
#define K_PAIRS 48   // K_TOT / 2

__device__ __forceinline__ float tanh_fast(float s) {
    // tanh(s) = 1 - 2/(exp(2s)+1); exact at +-inf saturation, ~1e-6 rel error via MUFU EX2/RCP
    float e = __expf(2.0f * s);
    return 1.0f - __fdividef(2.0f, e + 1.0f);
}

__global__ void __launch_bounds__(64) rnn_elman_kernel(
    const float* __restrict__ x,      // [N, T, I]
    const float* __restrict__ W_ih,   // [H, I]
    const float* __restrict__ W_hh,   // [H, H]
    const float* __restrict__ b_ih,   // [H]
    const float* __restrict__ b_hh,   // [H]
    const float* __restrict__ fc_w,   // [1, H]
    const float* __restrict__ fc_b,   // [1]
    float* __restrict__ out)          // [N, 1]
{
    __shared__ __align__(16) float buf[2][K_TOT];  // [parity][ h(64) | x_t(32) ]
    __shared__ float red[H_DIM];

    const int j = threadIdx.x;          // hidden unit index 0..63
    const int n = blockIdx.x;           // sample index

    // ---- Pack per-lane weights into 48 f32x2 register pairs ----
    // Layout of contraction axis: k=0..63 -> h (W_hh row j), k=64..95 -> x (W_ih row j)
    unsigned long long Wp[K_PAIRS];
    {
        const float* wr = W_hh + j * H_DIM;   // row j of W_hh (contig, 256B aligned)
        #pragma unroll
        for (int k = 0; k < 32; k++) {
            float2 t2 = *reinterpret_cast<const float2*>(wr + 2 * k);
            Wp[k] = *reinterpret_cast<unsigned long long*>(&t2);
        }
        const float* wi = W_ih + j * I_DIM;   // row j of W_ih
        #pragma unroll
        for (int k = 0; k < 16; k++) {
            float2 t2 = *reinterpret_cast<const float2*>(wi + 2 * k);
            Wp[32 + k] = *reinterpret_cast<unsigned long long*>(&t2);
        }
    }
    const float bias = b_ih[j] + b_hh[j];

    const float* xn_base = x + (size_t)n * T_STEPS * I_DIM;

    // ---- init: h0 = ones, stage x_0 ----
    buf[0][j] = 1.0f;
    if (j < I_DIM) buf[0][H_DIM + j] = xn_base[j];
    __syncthreads();

    float h = 1.0f;

    #pragma unroll 2
    for (int t = 0; t < T_STEPS; t++) {
        const int cur = t & 1;
        const int nxt = cur ^ 1;

        // prefetch next timestep's x early so LDG latency hides under the FMA loop
        float xnext = 0.0f;
        if (j < I_DIM && t + 1 < T_STEPS)
            xnext = __ldg(xn_base + (t + 1) * I_DIM + j);

        // ---- dot product: 48 x (LDS.64 broadcast + fma.rn.f32x2) ----
        const unsigned long long* bp =
            reinterpret_cast<const unsigned long long*>(&buf[cur][0]);

        float2 z0 = make_float2(bias, 0.0f);
        float2 zz = make_float2(0.0f, 0.0f);
        unsigned long long a0 = *reinterpret_cast<unsigned long long*>(&z0);
        unsigned long long a1 = *reinterpret_cast<unsigned long long*>(&zz);
        unsigned long long a2 = a1, a3 = a1;

        #pragma unroll
        for (int k = 0; k < K_PAIRS; k += 4) {
            asm("fma.rn.f32x2 %0, %1, %2, %0;" : "+l"(a0) : "l"(bp[k + 0]), "l"(Wp[k + 0]));
            asm("fma.rn.f32x2 %0, %1, %2, %0;" : "+l"(a1) : "l"(bp[k + 1]), "l"(Wp[k + 1]));
            asm("fma.rn.f32x2 %0, %1, %2, %0;" : "+l"(a2) : "l"(bp[k + 2]), "l"(Wp[k + 2]));
            asm("fma.rn.f32x2 %0, %1, %2, %0;" : "+l"(a3) : "l"(bp[k + 3]), "l"(Wp[k + 3]));
        }
        asm("add.rn.f32x2 %0, %0, %1;" : "+l"(a0) : "l"(a1));
        asm("add.rn.f32x2 %0, %0, %1;" : "+l"(a2) : "l"(a3));
        asm("add.rn.f32x2 %0, %0, %1;" : "+l"(a0) : "l"(a2));
        float2 r = *reinterpret_cast<float2*>(&a0);
        float s = r.x + r.y;

        h = tanh_fast(s);

        // publish h (and next x) into the other parity buffer; one barrier per step
        buf[nxt][j] = h;
        if (j < I_DIM && t + 1 < T_STEPS) buf[nxt][H_DIM + j] = xnext;
        __syncthreads();
    }

    // ---- output head: sigmoid(h . fc_w + fc_b), O = 1 ----
    red[j] = h * fc_w[j];
    __syncthreads();
    if (j == 0) {
        float s = fc_b[0];
        #pragma unroll
        for (int k = 0; k < H_DIM; k++) s += red[k];
        out[n] = __fdividef(1.0f, 1.0f + __expf(-s));
    }
}

extern "C" void kernel_launch(void* const* d_in, const int* in_sizes, int n_in,
                              void* d_out, int out_size) {
    const float* x    = (const float*)d_in[0];
    const float* W_ih = (const float*)d_in[1];
    const float* W_hh = (const float*)d_in[2];
    const float* b_ih = (const float*)d_in[3];
    const float* b_hh = (const float*)d_in[4];
    const float* fc_w = (const float*)d_in[5];
    const float* fc_b = (const float*)d_in[6];
    float* out = (float*)d_out;

    rnn_elman_kernel<<<2048, 64>>>(x, W_ih, W_hh, b_ih, b_hh, fc_w, fc_b, out);
}

// round 2
// speedup vs baseline: 1.2871x; 1.2871x over previous
#include <cuda_runtime.h>
#include <cstdint>

// Elman RNN, warp-per-sample layout.
// N=2048 samples, T=512, I=32, H=64, O=1.
// One 32-thread block per sample. Lane l owns hidden units (2l, 2l+1).
// Weights (96 f32x2 pairs per lane = 192 regs) in registers.
// Operand vector [h(64) | x_t(32)] double-buffered in smem, read as LDS.128,
// software-pipelined depth 4. One __syncwarp per timestep. fma.rn.f32x2 math.

#define TT 512
#define NSAMP 2048

typedef unsigned long long ull;

__device__ __forceinline__ float tanh_acc(float s) {
    // tanh(s) = 1 - 2/(exp(2s)+1): 2 MUFU + 3 fma-class ops, ~1e-7 rel err
    float e = __expf(2.0f * s);
    return 1.0f - __fdividef(2.0f, e + 1.0f);
}

__global__ void __launch_bounds__(32, 8) rnn_warp_kernel(
    const float* __restrict__ x,      // [N, T, I]
    const float* __restrict__ W_ih,   // [H, I]
    const float* __restrict__ W_hh,   // [H, H]
    const float* __restrict__ b_ih,   // [H]
    const float* __restrict__ b_hh,   // [H]
    const float* __restrict__ fc_w,   // [1, H]
    const float* __restrict__ fc_b,   // [1]
    float* __restrict__ out)          // [N, 1]
{
    __shared__ __align__(16) float buf[2][96];   // [parity][ h(64) | x_t(32) ]

    const int l  = threadIdx.x;      // lane 0..31
    const int n  = blockIdx.x;       // sample
    const int u0 = 2 * l;            // this lane's hidden units
    const int u1 = u0 + 1;

    // ---- load per-lane weights into registers as f32x2 pairs ----
    // contraction order: k=0..63 -> h (W_hh row), k=64..95 -> x (W_ih row)
    ull W0[48], W1[48];
    {
        const ull* p0 = reinterpret_cast<const ull*>(W_hh + u0 * 64);
        const ull* p1 = reinterpret_cast<const ull*>(W_hh + u1 * 64);
        #pragma unroll
        for (int k = 0; k < 32; k++) { W0[k] = __ldg(p0 + k); W1[k] = __ldg(p1 + k); }
        const ull* q0 = reinterpret_cast<const ull*>(W_ih + u0 * 32);
        const ull* q1 = reinterpret_cast<const ull*>(W_ih + u1 * 32);
        #pragma unroll
        for (int k = 0; k < 16; k++) { W0[32 + k] = __ldg(q0 + k); W1[32 + k] = __ldg(q1 + k); }
    }
    const float bi0 = b_ih[u0] + b_hh[u0];
    const float bi1 = b_ih[u1] + b_hh[u1];

    const float* xl = x + (size_t)n * TT * 32 + l;   // this lane's x column

    // ---- init: h0 = ones, stage x_0 ----
    *reinterpret_cast<float2*>(&buf[0][u0]) = make_float2(1.0f, 1.0f);
    buf[0][64 + l] = __ldg(xl);
    __syncwarp();

    float h0 = 1.0f, h1 = 1.0f;

    #pragma unroll 2
    for (int t = 0; t < TT; t++) {
        const int cur = t & 1;
        const int nxt = cur ^ 1;

        // prefetch next x early (coalesced 128B per warp); clamp at last step
        const int tn = (t + 1 < TT) ? (t + 1) : (TT - 1);
        const float xn = __ldg(xl + tn * 32);

        const ulonglong2* vp = reinterpret_cast<const ulonglong2*>(&buf[cur][0]);

        // accumulators: 2 f32x2 chains per unit, bias seeds chain 0
        float2 s0 = make_float2(bi0, 0.0f);
        float2 s1 = make_float2(bi1, 0.0f);
        ull a00 = *reinterpret_cast<ull*>(&s0);
        ull a01 = 0ull;
        ull a10 = *reinterpret_cast<ull*>(&s1);
        ull a11 = 0ull;

        // depth-4 pipelined LDS.128: prefetch distance ~16 instrs >= LDS latency
        ulonglong2 V[4];
        #pragma unroll
        for (int i = 0; i < 4; i++) V[i] = vp[i];

        #pragma unroll
        for (int g = 0; g < 24; g++) {
            ull lo = V[g & 3].x;
            ull hi = V[g & 3].y;
            if (g + 4 < 24) V[g & 3] = vp[g + 4];
            asm("fma.rn.f32x2 %0, %1, %2, %0;" : "+l"(a00) : "l"(lo), "l"(W0[2 * g]));
            asm("fma.rn.f32x2 %0, %1, %2, %0;" : "+l"(a01) : "l"(hi), "l"(W0[2 * g + 1]));
            asm("fma.rn.f32x2 %0, %1, %2, %0;" : "+l"(a10) : "l"(lo), "l"(W1[2 * g]));
            asm("fma.rn.f32x2 %0, %1, %2, %0;" : "+l"(a11) : "l"(hi), "l"(W1[2 * g + 1]));
        }

        asm("add.rn.f32x2 %0, %0, %1;" : "+l"(a00) : "l"(a01));
        asm("add.rn.f32x2 %0, %0, %1;" : "+l"(a10) : "l"(a11));
        float r0x, r0y, r1x, r1y;
        asm("mov.b64 {%0, %1}, %2;" : "=f"(r0x), "=f"(r0y) : "l"(a00));
        asm("mov.b64 {%0, %1}, %2;" : "=f"(r1x), "=f"(r1y) : "l"(a10));

        h0 = tanh_acc(r0x + r0y);
        h1 = tanh_acc(r1x + r1y);

        // publish h pair (one STS.64) + next x; one syncwarp per step
        *reinterpret_cast<float2*>(&buf[nxt][u0]) = make_float2(h0, h1);
        buf[nxt][64 + l] = xn;
        __syncwarp();
    }

    // ---- output head: sigmoid(h . fc_w + fc_b), warp shuffle reduction ----
    float part = h0 * fc_w[u0] + h1 * fc_w[u1];
    #pragma unroll
    for (int o = 16; o; o >>= 1) part += __shfl_xor_sync(0xffffffffu, part, o);
    if (l == 0)
        out[n] = __fdividef(1.0f, 1.0f + __expf(-(part + fc_b[0])));
}

extern "C" void kernel_launch(void* const* d_in, const int* in_sizes, int n_in,
                              void* d_out, int out_size) {
    const float* x    = (const float*)d_in[0];
    const float* W_ih = (const float*)d_in[1];
    const float* W_hh = (const float*)d_in[2];
    const float* b_ih = (const float*)d_in[3];
    const float* b_hh = (const float*)d_in[4];
    const float* fc_w = (const float*)d_in[5];
    const float* fc_b = (const float*)d_in[6];
    float* out = (float*)d_out;

    rnn_warp_kernel<<<NSAMP, 32>>>(x, W_ih, W_hh, b_ih, b_hh, fc_w, fc_b, out);
}

// round 3
// speedup vs baseline: 1.4124x; 1.0974x over previous
#include <cuda_runtime.h>
#include <cstdint>

// Elman RNN, warp-per-2-samples layout.
// N=2048, T=512, I=32, H=64, O=1.
// 1024 blocks x 32 threads (one warp). Lane l owns hidden units (2l, 2l+1)
// for BOTH samples (weights are sample-invariant -> 192 weight regs reused).
// Operand vectors [h(64)|x(32)] per sample, double-buffered in smem, LDS.128,
// depth-2 software pipeline per sample. One __syncwarp per timestep.

#define TT 512

typedef unsigned long long ull;

__device__ __forceinline__ float tanh_acc(float s) {
    float e = __expf(2.0f * s);
    return 1.0f - __fdividef(2.0f, e + 1.0f);
}

__global__ void __launch_bounds__(32, 8) rnn_warp2_kernel(
    const float* __restrict__ x,      // [N, T, I]
    const float* __restrict__ W_ih,   // [H, I]
    const float* __restrict__ W_hh,   // [H, H]
    const float* __restrict__ b_ih,   // [H]
    const float* __restrict__ b_hh,   // [H]
    const float* __restrict__ fc_w,   // [1, H]
    const float* __restrict__ fc_b,   // [1]
    float* __restrict__ out)          // [N, 1]
{
    __shared__ __align__(16) float buf[2][2][96];  // [parity][sample][ h(64)|x(32) ]

    const int l  = threadIdx.x;
    const int n0 = 2 * blockIdx.x;
    const int n1 = n0 + 1;
    const int u0 = 2 * l;
    const int u1 = u0 + 1;

    // ---- per-lane weights as f32x2 pairs: k=0..63 -> W_hh row, 64..95 -> W_ih row ----
    ull W0[48], W1[48];
    {
        const ull* p0 = reinterpret_cast<const ull*>(W_hh + u0 * 64);
        const ull* p1 = reinterpret_cast<const ull*>(W_hh + u1 * 64);
        #pragma unroll
        for (int k = 0; k < 32; k++) { W0[k] = __ldg(p0 + k); W1[k] = __ldg(p1 + k); }
        const ull* q0 = reinterpret_cast<const ull*>(W_ih + u0 * 32);
        const ull* q1 = reinterpret_cast<const ull*>(W_ih + u1 * 32);
        #pragma unroll
        for (int k = 0; k < 16; k++) { W0[32 + k] = __ldg(q0 + k); W1[32 + k] = __ldg(q1 + k); }
    }
    const float bi0 = b_ih[u0] + b_hh[u0];
    const float bi1 = b_ih[u1] + b_hh[u1];

    const float* xl0 = x + (size_t)n0 * TT * 32 + l;
    const float* xl1 = x + (size_t)n1 * TT * 32 + l;

    // ---- init: h0 = ones, stage x_0 for both samples ----
    *reinterpret_cast<float2*>(&buf[0][0][u0]) = make_float2(1.0f, 1.0f);
    *reinterpret_cast<float2*>(&buf[0][1][u0]) = make_float2(1.0f, 1.0f);
    buf[0][0][64 + l] = __ldg(xl0);
    buf[0][1][64 + l] = __ldg(xl1);
    __syncwarp();

    float h00 = 1.0f, h01 = 1.0f;   // sample0: units u0,u1
    float h10 = 1.0f, h11 = 1.0f;   // sample1

    #pragma unroll 2
    for (int t = 0; t < TT; t++) {
        const int cur = t & 1;
        const int nxt = cur ^ 1;

        // prefetch next x for both samples (coalesced 128B LDGs)
        const int tn = (t + 1 < TT) ? (t + 1) : (TT - 1);
        const float xn0 = __ldg(xl0 + tn * 32);
        const float xn1 = __ldg(xl1 + tn * 32);

        const ulonglong2* vp0 = reinterpret_cast<const ulonglong2*>(&buf[cur][0][0]);
        const ulonglong2* vp1 = reinterpret_cast<const ulonglong2*>(&buf[cur][1][0]);

        // one f32x2 accumulator chain per (sample, unit); bias seeds lo half
        float2 s0 = make_float2(bi0, 0.0f);
        float2 s1 = make_float2(bi1, 0.0f);
        ull a00 = *reinterpret_cast<ull*>(&s0);   // sample0 unit0
        ull a01 = *reinterpret_cast<ull*>(&s1);   // sample0 unit1
        ull a10 = a00;                            // sample1 unit0
        ull a11 = a01;                            // sample1 unit1

        // depth-2 pipelined LDS.128 per sample (load->use distance ~2 group bodies)
        ulonglong2 V0[2], V1[2];
        V0[0] = vp0[0]; V1[0] = vp1[0];
        V0[1] = vp0[1]; V1[1] = vp1[1];

        #pragma unroll
        for (int g = 0; g < 24; g++) {
            const ull lo0 = V0[g & 1].x, hi0 = V0[g & 1].y;
            const ull lo1 = V1[g & 1].x, hi1 = V1[g & 1].y;
            if (g + 2 < 24) { V0[g & 1] = vp0[g + 2]; V1[g & 1] = vp1[g + 2]; }
            asm("fma.rn.f32x2 %0, %1, %2, %0;" : "+l"(a00) : "l"(lo0), "l"(W0[2 * g]));
            asm("fma.rn.f32x2 %0, %1, %2, %0;" : "+l"(a01) : "l"(lo0), "l"(W1[2 * g]));
            asm("fma.rn.f32x2 %0, %1, %2, %0;" : "+l"(a10) : "l"(lo1), "l"(W0[2 * g]));
            asm("fma.rn.f32x2 %0, %1, %2, %0;" : "+l"(a11) : "l"(lo1), "l"(W1[2 * g]));
            asm("fma.rn.f32x2 %0, %1, %2, %0;" : "+l"(a00) : "l"(hi0), "l"(W0[2 * g + 1]));
            asm("fma.rn.f32x2 %0, %1, %2, %0;" : "+l"(a01) : "l"(hi0), "l"(W1[2 * g + 1]));
            asm("fma.rn.f32x2 %0, %1, %2, %0;" : "+l"(a10) : "l"(hi1), "l"(W0[2 * g + 1]));
            asm("fma.rn.f32x2 %0, %1, %2, %0;" : "+l"(a11) : "l"(hi1), "l"(W1[2 * g + 1]));
        }

        float r0x, r0y, r1x, r1y, r2x, r2y, r3x, r3y;
        asm("mov.b64 {%0, %1}, %2;" : "=f"(r0x), "=f"(r0y) : "l"(a00));
        asm("mov.b64 {%0, %1}, %2;" : "=f"(r1x), "=f"(r1y) : "l"(a01));
        asm("mov.b64 {%0, %1}, %2;" : "=f"(r2x), "=f"(r2y) : "l"(a10));
        asm("mov.b64 {%0, %1}, %2;" : "=f"(r3x), "=f"(r3y) : "l"(a11));

        h00 = tanh_acc(r0x + r0y);
        h01 = tanh_acc(r1x + r1y);
        h10 = tanh_acc(r2x + r2y);
        h11 = tanh_acc(r3x + r3y);

        *reinterpret_cast<float2*>(&buf[nxt][0][u0]) = make_float2(h00, h01);
        *reinterpret_cast<float2*>(&buf[nxt][1][u0]) = make_float2(h10, h11);
        buf[nxt][0][64 + l] = xn0;
        buf[nxt][1][64 + l] = xn1;
        __syncwarp();
    }

    // ---- output heads: sigmoid(h . fc_w + fc_b) per sample ----
    const float w0 = fc_w[u0], w1 = fc_w[u1];
    float p0 = h00 * w0 + h01 * w1;
    float p1 = h10 * w0 + h11 * w1;
    #pragma unroll
    for (int o = 16; o; o >>= 1) {
        p0 += __shfl_xor_sync(0xffffffffu, p0, o);
        p1 += __shfl_xor_sync(0xffffffffu, p1, o);
    }
    if (l == 0) {
        const float fb = fc_b[0];
        out[n0] = __fdividef(1.0f, 1.0f + __expf(-(p0 + fb)));
        out[n1] = __fdividef(1.0f, 1.0f + __expf(-(p1 + fb)));
    }
}

extern "C" void kernel_launch(void* const* d_in, const int* in_sizes, int n_in,
                              void* d_out, int out_size) {
    const float* x    = (const float*)d_in[0];
    const float* W_ih = (const float*)d_in[1];
    const float* W_hh = (const float*)d_in[2];
    const float* b_ih = (const float*)d_in[3];
    const float* b_hh = (const float*)d_in[4];
    const float* fc_w = (const float*)d_in[5];
    const float* fc_b = (const float*)d_in[6];
    float* out = (float*)d_out;

    rnn_warp2_kernel<<<1024, 32>>>(x, W_ih, W_hh, b_ih, b_hh, fc_w, fc_b, out);
}